// round 2
// baseline (speedup 1.0000x reference)
#include <cuda_runtime.h>
#include <cuda_bf16.h>
#include <math.h>

// Problem constants
#define Bsz 1024
#define Tsz 128
#define Fsz 9
#define Hsz 256
#define Psz 2048
#define NHEADS 4
#define DHEAD 64
#define BT (Bsz*Tsz)

// ---------------- scratch (static device globals; no allocation) ----------------
__device__ float g_h[BT * Hsz];        // 134 MB : VSN out / LSTM hseq
__device__ float g_xp[BT * 4 * Hsz];   // 537 MB : xp precompute / later kv buffer
__device__ float g_c[Bsz * Hsz];       // LSTM cell state
__device__ float g_q[Bsz * Hsz];
__device__ float g_o[Bsz * Hsz];
__device__ float g_hidden[Bsz * Hsz];
__device__ float g_pe[Psz * Hsz];
__device__ float g_degs[Psz];
__device__ float g_agg[Psz * Hsz];
__device__ float g_trans[Psz * Hsz];

__device__ __forceinline__ float sigmoidf_(float x) { return 1.0f / (1.0f + expf(-x)); }

// ---------------- VSN: per (b,t) softmax-weighted embedding ----------------
__global__ __launch_bounds__(256) void vsn_kernel(
    const float* __restrict__ x,
    const float* __restrict__ emb_w, const float* __restrict__ emb_b,
    const float* __restrict__ sel_w, const float* __restrict__ sel_b,
    float* __restrict__ h)
{
    int bt = blockIdx.x;
    int tid = threadIdx.x;  // 256
    __shared__ float xs[Fsz];
    __shared__ float wts[Fsz];
    if (tid < Fsz) xs[tid] = x[(size_t)bt * Fsz + tid];
    __syncthreads();
    if (tid == 0) {
        float lg[Fsz]; float mx = -1e30f;
        for (int f = 0; f < Fsz; f++) {
            float s = sel_b[f];
            for (int j = 0; j < Fsz; j++) s += xs[j] * sel_w[f * Fsz + j];
            lg[f] = s; mx = fmaxf(mx, s);
        }
        float den = 0.f;
        for (int f = 0; f < Fsz; f++) { lg[f] = expf(lg[f] - mx); den += lg[f]; }
        float inv = 1.0f / den;
        for (int f = 0; f < Fsz; f++) wts[f] = lg[f] * inv;
    }
    __syncthreads();
    float acc = 0.f;
#pragma unroll
    for (int f = 0; f < Fsz; f++)
        acc += wts[f] * (xs[f] * emb_w[f * Hsz + tid] + emb_b[f * Hsz + tid]);
    h[(size_t)bt * Hsz + tid] = acc;
}

// ---------------- generic NT SGEMM: C[m,n] = sum_k A[m,k]*W[n,k] + b1[n] + b2[n] ----------------
__global__ __launch_bounds__(256) void sgemm_nt(
    const float* __restrict__ A, const float* __restrict__ W,
    const float* __restrict__ b1, const float* __restrict__ b2,
    float* __restrict__ C, int M, int N, int K)
{
    __shared__ float As[16][64];
    __shared__ float Bs[16][64];
    const int tid = threadIdx.x;
    const int m0 = blockIdx.y * 64;
    const int n0 = blockIdx.x * 64;
    const int lr = tid >> 2;          // 0..63
    const int lc = (tid & 3) << 2;    // 0,4,8,12
    const int ty = tid >> 4, tx = tid & 15;
    float acc[4][4] = {};
    for (int k0 = 0; k0 < K; k0 += 16) {
        float4 a = *(const float4*)&A[(size_t)(m0 + lr) * K + k0 + lc];
        float4 w = *(const float4*)&W[(size_t)(n0 + lr) * K + k0 + lc];
        As[lc + 0][lr] = a.x; As[lc + 1][lr] = a.y; As[lc + 2][lr] = a.z; As[lc + 3][lr] = a.w;
        Bs[lc + 0][lr] = w.x; Bs[lc + 1][lr] = w.y; Bs[lc + 2][lr] = w.z; Bs[lc + 3][lr] = w.w;
        __syncthreads();
#pragma unroll
        for (int kk = 0; kk < 16; kk++) {
            float ra[4], rb[4];
#pragma unroll
            for (int i = 0; i < 4; i++) ra[i] = As[kk][ty * 4 + i];
#pragma unroll
            for (int j = 0; j < 4; j++) rb[j] = Bs[kk][tx * 4 + j];
#pragma unroll
            for (int i = 0; i < 4; i++)
#pragma unroll
                for (int j = 0; j < 4; j++) acc[i][j] += ra[i] * rb[j];
        }
        __syncthreads();
    }
#pragma unroll
    for (int i = 0; i < 4; i++) {
        int m = m0 + ty * 4 + i;
#pragma unroll
        for (int j = 0; j < 4; j++) {
            int n = n0 + tx * 4 + j;
            float v = acc[i][j];
            if (b1) v += b1[n];
            if (b2) v += b2[n];
            C[(size_t)m * N + n] = v;
        }
    }
}

// ---------------- NN SGEMM with row scaling: C[m,n] = s[m] * sum_k A[m,k]*Bm[k,n] ----------------
__global__ __launch_bounds__(256) void sgemm_nn_scale(
    const float* __restrict__ A, const float* __restrict__ Bm,
    const float* __restrict__ rowscale,
    float* __restrict__ C, int M, int N, int K)
{
    __shared__ float As[16][64];
    __shared__ float Bs[16][64];
    const int tid = threadIdx.x;
    const int m0 = blockIdx.y * 64;
    const int n0 = blockIdx.x * 64;
    const int lr = tid >> 2;
    const int lc = (tid & 3) << 2;
    const int br = tid >> 4;            // 0..15 (kk)
    const int bc = (tid & 15) << 2;     // 0..60
    const int ty = tid >> 4, tx = tid & 15;
    float acc[4][4] = {};
    for (int k0 = 0; k0 < K; k0 += 16) {
        float4 a = *(const float4*)&A[(size_t)(m0 + lr) * K + k0 + lc];
        float4 b = *(const float4*)&Bm[(size_t)(k0 + br) * N + n0 + bc];
        As[lc + 0][lr] = a.x; As[lc + 1][lr] = a.y; As[lc + 2][lr] = a.z; As[lc + 3][lr] = a.w;
        Bs[br][bc + 0] = b.x; Bs[br][bc + 1] = b.y; Bs[br][bc + 2] = b.z; Bs[br][bc + 3] = b.w;
        __syncthreads();
#pragma unroll
        for (int kk = 0; kk < 16; kk++) {
            float ra[4], rb[4];
#pragma unroll
            for (int i = 0; i < 4; i++) ra[i] = As[kk][ty * 4 + i];
#pragma unroll
            for (int j = 0; j < 4; j++) rb[j] = Bs[kk][tx * 4 + j];
#pragma unroll
            for (int i = 0; i < 4; i++)
#pragma unroll
                for (int j = 0; j < 4; j++) acc[i][j] += ra[i] * rb[j];
        }
        __syncthreads();
    }
#pragma unroll
    for (int i = 0; i < 4; i++) {
        int m = m0 + ty * 4 + i;
        float sc = rowscale[m];
#pragma unroll
        for (int j = 0; j < 4; j++) {
            int n = n0 + tx * 4 + j;
            C[(size_t)m * N + n] = sc * acc[i][j];
        }
    }
}

// ---------------- Fused LSTM step ----------------
// grid (8, 16): x=j tile (32 cols of H), y=b tile (64 rows). 256 threads.
// t==0: c initialized to 0 internally (no memset needed, no h@Whh term).
__global__ __launch_bounds__(256) void lstm_step(
    const float* __restrict__ xp, float* __restrict__ hseq,
    const float* __restrict__ Whh, float* __restrict__ c, int t)
{
    __shared__ float Hs[16][64];
    __shared__ float Ws[16][128];
    const int tid = threadIdx.x;
    const int j0 = blockIdx.x * 32;
    const int b0 = blockIdx.y * 64;
    const int ty = tid >> 4, tx = tid & 15;
    float acc[4][4][2] = {};
    if (t > 0) {
        const int lr = tid >> 2, lc = (tid & 3) << 2;
        const int wr = tid >> 1, wc = (tid & 1) << 3;
        const int wg = wr >> 5, wj = wr & 31;
        const float* wbase = &Whh[(size_t)(wg * Hsz + j0 + wj) * Hsz];
        const float* hbase = &hseq[((size_t)(b0 + lr) * Tsz + (t - 1)) * Hsz];
        for (int k0 = 0; k0 < Hsz; k0 += 16) {
            float4 hv = *(const float4*)&hbase[k0 + lc];
            Hs[lc + 0][lr] = hv.x; Hs[lc + 1][lr] = hv.y; Hs[lc + 2][lr] = hv.z; Hs[lc + 3][lr] = hv.w;
            float4 w0 = *(const float4*)&wbase[k0 + wc];
            float4 w1 = *(const float4*)&wbase[k0 + wc + 4];
            Ws[wc + 0][wr] = w0.x; Ws[wc + 1][wr] = w0.y; Ws[wc + 2][wr] = w0.z; Ws[wc + 3][wr] = w0.w;
            Ws[wc + 4][wr] = w1.x; Ws[wc + 5][wr] = w1.y; Ws[wc + 6][wr] = w1.z; Ws[wc + 7][wr] = w1.w;
            __syncthreads();
#pragma unroll
            for (int kk = 0; kk < 16; kk++) {
                float rh[4], rw[4][2];
#pragma unroll
                for (int m = 0; m < 4; m++) rh[m] = Hs[kk][ty * 4 + m];
#pragma unroll
                for (int g = 0; g < 4; g++) {
                    rw[g][0] = Ws[kk][g * 32 + tx * 2];
                    rw[g][1] = Ws[kk][g * 32 + tx * 2 + 1];
                }
#pragma unroll
                for (int m = 0; m < 4; m++)
#pragma unroll
                    for (int g = 0; g < 4; g++) {
                        acc[m][g][0] += rh[m] * rw[g][0];
                        acc[m][g][1] += rh[m] * rw[g][1];
                    }
            }
            __syncthreads();
        }
    }
#pragma unroll
    for (int m = 0; m < 4; m++) {
        int b = b0 + ty * 4 + m;
#pragma unroll
        for (int jj = 0; jj < 2; jj++) {
            int j = j0 + tx * 2 + jj;
            size_t xbase = ((size_t)b * Tsz + t) * (4 * Hsz) + j;
            float gi = acc[m][0][jj] + xp[xbase];
            float gf = acc[m][1][jj] + xp[xbase + Hsz];
            float gg = acc[m][2][jj] + xp[xbase + 2 * Hsz];
            float go = acc[m][3][jj] + xp[xbase + 3 * Hsz];
            float co = (t == 0) ? 0.0f : c[b * Hsz + j];
            float cn = sigmoidf_(gf) * co + sigmoidf_(gi) * tanhf(gg);
            float hn = sigmoidf_(go) * tanhf(cn);
            c[b * Hsz + j] = cn;
            hseq[((size_t)b * Tsz + t) * Hsz + j] = hn;
        }
    }
}

// ---------------- q projection at last timestep only ----------------
__global__ __launch_bounds__(256) void qproj_kernel(
    const float* __restrict__ h, const float* __restrict__ Wq,
    const float* __restrict__ bq, float* __restrict__ q)
{
    int b = blockIdx.x, tid = threadIdx.x;  // 256
    __shared__ float hs[Hsz];
    hs[tid] = h[((size_t)b * Tsz + (Tsz - 1)) * Hsz + tid];
    __syncthreads();
    float s = bq[tid];
    const float* wrow = &Wq[(size_t)tid * Hsz];
#pragma unroll 8
    for (int k = 0; k < Hsz; k++) s += hs[k] * wrow[k];
    q[(size_t)b * Hsz + tid] = s;
}

// ---------------- attention, last query position only ----------------
__global__ __launch_bounds__(128) void attn_last_kernel(
    const float* __restrict__ q, const float* __restrict__ kv,
    float* __restrict__ o)
{
    int b = blockIdx.x, hd = blockIdx.y;
    int tid = threadIdx.x;  // 128
    __shared__ float qs[DHEAD];
    __shared__ float sc[Tsz];
    __shared__ float red[Tsz];
    if (tid < DHEAD) qs[tid] = q[(size_t)b * Hsz + hd * DHEAD + tid];
    __syncthreads();
    const float* kp = &kv[((size_t)b * Tsz + tid) * 512 + hd * DHEAD];
    float s = 0.f;
#pragma unroll 8
    for (int d = 0; d < DHEAD; d++) s += qs[d] * kp[d];
    s *= 0.125f;  // 1/sqrt(64)
    sc[tid] = s;
    red[tid] = s;
    __syncthreads();
    for (int off = 64; off; off >>= 1) {
        if (tid < off) red[tid] = fmaxf(red[tid], red[tid + off]);
        __syncthreads();
    }
    float mx = red[0];
    __syncthreads();
    float e = expf(sc[tid] - mx);
    sc[tid] = e;
    red[tid] = e;
    __syncthreads();
    for (int off = 64; off; off >>= 1) {
        if (tid < off) red[tid] += red[tid + off];
        __syncthreads();
    }
    float inv = 1.0f / red[0];
    __syncthreads();
    sc[tid] *= inv;
    __syncthreads();
    if (tid < DHEAD) {
        float acc = 0.f;
        for (int t = 0; t < Tsz; t++)
            acc += sc[t] * kv[((size_t)b * Tsz + t) * 512 + 256 + hd * DHEAD + tid];
        o[(size_t)b * Hsz + hd * DHEAD + tid] = acc;
    }
}

// ---------------- GNN helpers ----------------
__global__ __launch_bounds__(256) void scatter_kernel(
    const float* __restrict__ hidden, const int* __restrict__ sku,
    float* __restrict__ pe)
{
    int b = blockIdx.x, tid = threadIdx.x;
    pe[(size_t)sku[b] * Hsz + tid] = hidden[(size_t)b * Hsz + tid];
}

__global__ __launch_bounds__(256) void deg_kernel(
    const float* __restrict__ adj, float* __restrict__ scale)
{
    int p = blockIdx.x, tid = threadIdx.x;  // 256
    float s = 0.f;
    for (int j = tid; j < Psz; j += 256) s += adj[(size_t)p * Psz + j];
    __shared__ float red[256];
    red[tid] = s; __syncthreads();
    for (int off = 128; off; off >>= 1) {
        if (tid < off) red[tid] += red[tid + off];
        __syncthreads();
    }
    if (tid == 0) scale[p] = 1.0f / fmaxf(red[0], 1e-6f);
}

__global__ __launch_bounds__(256) void geluln_kernel(
    float* __restrict__ x, const float* __restrict__ g,
    const float* __restrict__ b)
{
    int p = blockIdx.x, tid = threadIdx.x;  // 256
    float v = x[(size_t)p * Hsz + tid];
    float ge = 0.5f * v * (1.0f + erff(v * 0.70710678118654752f));
    __shared__ float red[256];
    red[tid] = ge; __syncthreads();
    for (int off = 128; off; off >>= 1) {
        if (tid < off) red[tid] += red[tid + off];
        __syncthreads();
    }
    float mu = red[0] * (1.0f / Hsz);
    __syncthreads();
    float d = ge - mu;
    red[tid] = d * d; __syncthreads();
    for (int off = 128; off; off >>= 1) {
        if (tid < off) red[tid] += red[tid + off];
        __syncthreads();
    }
    float var = red[0] * (1.0f / Hsz);
    x[(size_t)p * Hsz + tid] = d * rsqrtf(var + 1e-5f) * g[tid] + b[tid];
}

// ---------------- gate + output head ----------------
__global__ __launch_bounds__(256) void final_kernel(
    const float* __restrict__ hidden, const float* __restrict__ trans,
    const int* __restrict__ sku,
    const float* __restrict__ gate_w, const float* __restrict__ gate_b,
    const float* __restrict__ out_w, const float* __restrict__ out_b,
    float* __restrict__ out)
{
    int b = blockIdx.x, tid = threadIdx.x;  // 256
    __shared__ float cat[512];
    cat[tid] = hidden[(size_t)b * Hsz + tid];
    cat[256 + tid] = trans[(size_t)sku[b] * Hsz + tid];
    __syncthreads();
    float s = gate_b[tid];
    const float* wrow = &gate_w[(size_t)tid * 512];
#pragma unroll 8
    for (int k = 0; k < 512; k++) s += cat[k] * wrow[k];
    float gt = 1.0f / (1.0f + expf(-s));
    float comb = gt * cat[256 + tid] + (1.0f - gt) * cat[tid];
    __shared__ float red[256];
    red[tid] = comb * out_w[tid];
    __syncthreads();
    for (int off = 128; off; off >>= 1) {
        if (tid < off) red[tid] += red[tid + off];
        __syncthreads();
    }
    if (tid == 0) out[b] = red[0] + out_b[0];
}

// ---------------- launch ----------------
extern "C" void kernel_launch(void* const* d_in, const int* in_sizes, int n_in,
                              void* d_out, int out_size)
{
    const float* x          = (const float*)d_in[0];
    const int*   sku        = (const int*)  d_in[1];
    const float* adj        = (const float*)d_in[2];
    const float* vsn_emb_w  = (const float*)d_in[3];
    const float* vsn_emb_b  = (const float*)d_in[4];
    const float* vsn_sel_w  = (const float*)d_in[5];
    const float* vsn_sel_b  = (const float*)d_in[6];
    const float* Wih0       = (const float*)d_in[7];
    const float* Whh0       = (const float*)d_in[8];
    const float* bih0       = (const float*)d_in[9];
    const float* bhh0       = (const float*)d_in[10];
    const float* Wih1       = (const float*)d_in[11];
    const float* Whh1       = (const float*)d_in[12];
    const float* bih1       = (const float*)d_in[13];
    const float* bhh1       = (const float*)d_in[14];
    const float* attn_in_w  = (const float*)d_in[15];
    const float* attn_in_b  = (const float*)d_in[16];
    const float* attn_out_w = (const float*)d_in[17];
    const float* attn_out_b = (const float*)d_in[18];
    const float* gnn_w      = (const float*)d_in[19];
    const float* gnn_b      = (const float*)d_in[20];
    const float* ln_g       = (const float*)d_in[21];
    const float* ln_b       = (const float*)d_in[22];
    const float* gate_w     = (const float*)d_in[23];
    const float* gate_b     = (const float*)d_in[24];
    const float* out_w      = (const float*)d_in[25];
    const float* out_b      = (const float*)d_in[26];
    float* out = (float*)d_out;

    static float *hP = nullptr, *xpP, *cP, *qP, *oP, *hidP, *peP, *degP, *aggP, *transP;
    if (!hP) {
        cudaGetSymbolAddress((void**)&hP, g_h);
        cudaGetSymbolAddress((void**)&xpP, g_xp);
        cudaGetSymbolAddress((void**)&cP, g_c);
        cudaGetSymbolAddress((void**)&qP, g_q);
        cudaGetSymbolAddress((void**)&oP, g_o);
        cudaGetSymbolAddress((void**)&hidP, g_hidden);
        cudaGetSymbolAddress((void**)&degP, g_degs);
        cudaGetSymbolAddress((void**)&peP, g_pe);
        cudaGetSymbolAddress((void**)&aggP, g_agg);
        cudaGetSymbolAddress((void**)&transP, g_trans);
    }

    // 1. VSN -> g_h (BT, H)
    vsn_kernel<<<BT, 256>>>(x, vsn_emb_w, vsn_emb_b, vsn_sel_w, vsn_sel_b, hP);

    // 2. LSTM layer 0: xp = h @ Wih0^T + bih0 + bhh0 ; recurrence
    sgemm_nt<<<dim3(4 * Hsz / 64, BT / 64), 256>>>(hP, Wih0, bih0, bhh0, xpP, BT, 4 * Hsz, Hsz);
    for (int t = 0; t < Tsz; t++)
        lstm_step<<<dim3(8, 16), 256>>>(xpP, hP, Whh0, cP, t);

    // 3. LSTM layer 1
    sgemm_nt<<<dim3(4 * Hsz / 64, BT / 64), 256>>>(hP, Wih1, bih1, bhh1, xpP, BT, 4 * Hsz, Hsz);
    for (int t = 0; t < Tsz; t++)
        lstm_step<<<dim3(8, 16), 256>>>(xpP, hP, Whh1, cP, t);

    // 4. k,v projection for all t -> reuse g_xp as (BT, 512); q only at last timestep
    sgemm_nt<<<dim3(512 / 64, BT / 64), 256>>>(hP, attn_in_w + (size_t)Hsz * Hsz,
                                               attn_in_b + Hsz, nullptr, xpP, BT, 512, Hsz);
    qproj_kernel<<<Bsz, 256>>>(hP, attn_in_w, attn_in_b, qP);

    // 5. attention at last query position
    attn_last_kernel<<<dim3(Bsz, NHEADS), 128>>>(qP, xpP, oP);

    // 6. output projection -> hidden (B, H)
    sgemm_nt<<<dim3(Hsz / 64, Bsz / 64), 256>>>(oP, attn_out_w, attn_out_b, nullptr,
                                                hidP, Bsz, Hsz, Hsz);

    // 7. GNN
    cudaMemsetAsync(peP, 0, (size_t)Psz * Hsz * sizeof(float));
    scatter_kernel<<<Bsz, 256>>>(hidP, sku, peP);
    deg_kernel<<<Psz, 256>>>(adj, degP);
    sgemm_nn_scale<<<dim3(Hsz / 64, Psz / 64), 256>>>(adj, peP, degP, aggP, Psz, Hsz, Psz);
    sgemm_nt<<<dim3(Hsz / 64, Psz / 64), 256>>>(aggP, gnn_w, gnn_b, nullptr, transP, Psz, Hsz, Hsz);
    geluln_kernel<<<Psz, 256>>>(transP, ln_g, ln_b);

    // 8. gate + head
    final_kernel<<<Bsz, 256>>>(hidP, transP, sku, gate_w, gate_b, out_w, out_b, out);
}

// round 4
// speedup vs baseline: 2.0878x; 2.0878x over previous
#include <cuda_runtime.h>
#include <cuda_bf16.h>
#include <math.h>
#include <stdint.h>

// Problem constants
#define Bsz 1024
#define Tsz 128
#define Fsz 9
#define Hsz 256
#define Psz 2048
#define NHEADS 4
#define DHEAD 64
#define BT (Bsz*Tsz)

// ---------------- scratch (static device globals; no allocation) ----------------
__device__ float g_h[BT * Hsz];        // VSN out / LSTM hseq  [b*T+t][256]
__device__ float g_xp[BT * 4 * Hsz];   // xp precompute / kv buffer [b*T+t][1024]
__device__ float g_c[Bsz * Hsz];       // LSTM cell state
__device__ float g_q[Bsz * Hsz];
__device__ float g_o[Bsz * Hsz];
__device__ float g_hidden[Bsz * Hsz];
__device__ float g_pe[Psz * Hsz];
__device__ float g_degs[Psz];
__device__ float g_agg[Psz * Hsz];
__device__ float g_trans[Psz * Hsz];

__device__ __forceinline__ float sigmoidf_(float x) { return 1.0f / (1.0f + expf(-x)); }

// ---------------- tf32 mma.sync helpers (target-independent PTX, sm_80+) ----------------
__device__ __forceinline__ uint32_t f2tf32(float f) {
    uint32_t r;
    asm("cvt.rna.tf32.f32 %0, %1;" : "=r"(r) : "f"(f));
    return r;
}
__device__ __forceinline__ void mma_m16n8k8(float d[4], const uint32_t a[4], const uint32_t b[2]) {
    asm volatile(
        "mma.sync.aligned.m16n8k8.row.col.f32.tf32.tf32.f32 "
        "{%0,%1,%2,%3}, {%4,%5,%6,%7}, {%8,%9}, {%0,%1,%2,%3};"
        : "+f"(d[0]), "+f"(d[1]), "+f"(d[2]), "+f"(d[3])
        : "r"(a[0]), "r"(a[1]), "r"(a[2]), "r"(a[3]), "r"(b[0]), "r"(b[1]));
}

// ================= mm_nt_tf32: C[m,n] = sum_k A[m,k]*W[n,k] + b1[n] + b2[n] =================
// CTA tile 128(M) x 64(N), K=256 in chunks of 32. 8 warps, warp tile 32x32.
// grid = (Nall/64, M/128).
__global__ __launch_bounds__(256) void mm_nt_tf32(
    const float* __restrict__ A, const float* __restrict__ W,
    const float* __restrict__ b1, const float* __restrict__ b2,
    float* __restrict__ C, int Nall)
{
    __shared__ __align__(16) uint32_t As[128][36];
    __shared__ __align__(16) uint32_t Bs[64][36];
    const int tid = threadIdx.x;
    const int wid = tid >> 5, lane = tid & 31;
    const int gID = lane >> 2, tig = lane & 3;
    const int wr = wid & 3, wc = wid >> 2;
    const int m0 = blockIdx.y * 128, n0 = blockIdx.x * 64;
    float d[2][4][4] = {};

    for (int k0 = 0; k0 < 256; k0 += 32) {
        #pragma unroll
        for (int i = 0; i < 4; i++) {
            int idx = tid + i * 256;
            int r = idx >> 3, cc = (idx & 7) << 2;
            float4 v = *(const float4*)&A[(size_t)(m0 + r) * 256 + k0 + cc];
            uint32_t* p = &As[r][cc];
            p[0] = f2tf32(v.x); p[1] = f2tf32(v.y); p[2] = f2tf32(v.z); p[3] = f2tf32(v.w);
        }
        #pragma unroll
        for (int i = 0; i < 2; i++) {
            int idx = tid + i * 256;
            int r = idx >> 3, cc = (idx & 7) << 2;
            float4 v = *(const float4*)&W[(size_t)(n0 + r) * 256 + k0 + cc];
            uint32_t* p = &Bs[r][cc];
            p[0] = f2tf32(v.x); p[1] = f2tf32(v.y); p[2] = f2tf32(v.z); p[3] = f2tf32(v.w);
        }
        __syncthreads();
        #pragma unroll
        for (int k8 = 0; k8 < 4; k8++) {
            uint32_t a[2][4], b[4][2];
            #pragma unroll
            for (int mi = 0; mi < 2; mi++) {
                int mr = wr * 32 + mi * 16;
                a[mi][0] = As[mr + gID][k8 * 8 + tig];
                a[mi][1] = As[mr + 8 + gID][k8 * 8 + tig];
                a[mi][2] = As[mr + gID][k8 * 8 + 4 + tig];
                a[mi][3] = As[mr + 8 + gID][k8 * 8 + 4 + tig];
            }
            #pragma unroll
            for (int ni = 0; ni < 4; ni++) {
                int nr = wc * 32 + ni * 8 + gID;
                b[ni][0] = Bs[nr][k8 * 8 + tig];
                b[ni][1] = Bs[nr][k8 * 8 + 4 + tig];
            }
            #pragma unroll
            for (int mi = 0; mi < 2; mi++)
                #pragma unroll
                for (int ni = 0; ni < 4; ni++)
                    mma_m16n8k8(d[mi][ni], a[mi], b[ni]);
        }
        __syncthreads();
    }
    #pragma unroll
    for (int mi = 0; mi < 2; mi++) {
        int m = m0 + wr * 32 + mi * 16 + gID;
        #pragma unroll
        for (int ni = 0; ni < 4; ni++) {
            int n = n0 + wc * 32 + ni * 8 + tig * 2;
            float bb0 = 0.f, bb1 = 0.f;
            if (b1) { bb0 += b1[n]; bb1 += b1[n + 1]; }
            if (b2) { bb0 += b2[n]; bb1 += b2[n + 1]; }
            C[(size_t)m * Nall + n]       = d[mi][ni][0] + bb0;
            C[(size_t)m * Nall + n + 1]   = d[mi][ni][1] + bb1;
            C[(size_t)(m + 8) * Nall + n]     = d[mi][ni][2] + bb0;
            C[(size_t)(m + 8) * Nall + n + 1] = d[mi][ni][3] + bb1;
        }
    }
}

// ================= lstm_tc: fused recurrence step (tf32 mma + cell update) =================
// grid (16 j-blocks, 8 b-tiles). CTA: M=128 batches x N=64 (4 gates x 16 j), K=256.
// Gate-interleaved B tile: n_local = gate*16 + jj, Whh row = gate*256 + j0 + jj.
__global__ __launch_bounds__(256) void lstm_tc(
    const float* __restrict__ xp, float* __restrict__ hseq,
    const float* __restrict__ Whh, float* __restrict__ c, int t)
{
    __shared__ __align__(16) char sbuf[34816];   // max(As+Bs = 27648, Cs = 34816)
    uint32_t (*As)[36] = (uint32_t(*)[36])sbuf;            // 128 x 36
    uint32_t (*Bs)[36] = (uint32_t(*)[36])(sbuf + 18432);  // 64 x 36
    float (*Cs)[68]    = (float(*)[68])sbuf;               // 128 x 68 (aliases As/Bs)

    const int tid = threadIdx.x;
    const int wid = tid >> 5, lane = tid & 31;
    const int gID = lane >> 2, tig = lane & 3;
    const int wr = wid & 3, wc = wid >> 2;
    const int j0 = blockIdx.x * 16;
    const int m0 = blockIdx.y * 128;
    float d[2][4][4] = {};

    for (int k0 = 0; k0 < 256; k0 += 32) {
        #pragma unroll
        for (int i = 0; i < 4; i++) {
            int idx = tid + i * 256;
            int r = idx >> 3, cc = (idx & 7) << 2;
            float4 v = *(const float4*)&hseq[((size_t)(m0 + r) * Tsz + (t - 1)) * 256 + k0 + cc];
            uint32_t* p = &As[r][cc];
            p[0] = f2tf32(v.x); p[1] = f2tf32(v.y); p[2] = f2tf32(v.z); p[3] = f2tf32(v.w);
        }
        #pragma unroll
        for (int i = 0; i < 2; i++) {
            int idx = tid + i * 256;
            int r = idx >> 3, cc = (idx & 7) << 2;   // r = n_local
            int wrow = (r >> 4) * 256 + j0 + (r & 15);
            float4 v = *(const float4*)&Whh[(size_t)wrow * 256 + k0 + cc];
            uint32_t* p = &Bs[r][cc];
            p[0] = f2tf32(v.x); p[1] = f2tf32(v.y); p[2] = f2tf32(v.z); p[3] = f2tf32(v.w);
        }
        __syncthreads();
        #pragma unroll
        for (int k8 = 0; k8 < 4; k8++) {
            uint32_t a[2][4], b[4][2];
            #pragma unroll
            for (int mi = 0; mi < 2; mi++) {
                int mr = wr * 32 + mi * 16;
                a[mi][0] = As[mr + gID][k8 * 8 + tig];
                a[mi][1] = As[mr + 8 + gID][k8 * 8 + tig];
                a[mi][2] = As[mr + gID][k8 * 8 + 4 + tig];
                a[mi][3] = As[mr + 8 + gID][k8 * 8 + 4 + tig];
            }
            #pragma unroll
            for (int ni = 0; ni < 4; ni++) {
                int nr = wc * 32 + ni * 8 + gID;
                b[ni][0] = Bs[nr][k8 * 8 + tig];
                b[ni][1] = Bs[nr][k8 * 8 + 4 + tig];
            }
            #pragma unroll
            for (int mi = 0; mi < 2; mi++)
                #pragma unroll
                for (int ni = 0; ni < 4; ni++)
                    mma_m16n8k8(d[mi][ni], a[mi], b[ni]);
        }
        __syncthreads();
    }

    // stage accumulators (recurrent gate contributions) into smem
    #pragma unroll
    for (int mi = 0; mi < 2; mi++) {
        int m = wr * 32 + mi * 16 + gID;
        #pragma unroll
        for (int ni = 0; ni < 4; ni++) {
            int n = wc * 32 + ni * 8 + tig * 2;
            *(float2*)&Cs[m][n]     = make_float2(d[mi][ni][0], d[mi][ni][1]);
            *(float2*)&Cs[m + 8][n] = make_float2(d[mi][ni][2], d[mi][ni][3]);
        }
    }
    __syncthreads();

    // fused cell update: thread -> (b_local = tid>>1, 8 j's)
    const int bl = tid >> 1;
    const int jj0 = (tid & 1) * 8;
    const int b = m0 + bl;
    const int jg = j0 + jj0;
    const float* xb = &xp[((size_t)b * Tsz + t) * 1024 + jg];
    float xi[8], xf[8], xg[8], xo[8], cold[8];
    *(float4*)&xi[0] = *(const float4*)&xb[0];    *(float4*)&xi[4] = *(const float4*)&xb[4];
    *(float4*)&xf[0] = *(const float4*)&xb[256];  *(float4*)&xf[4] = *(const float4*)&xb[260];
    *(float4*)&xg[0] = *(const float4*)&xb[512];  *(float4*)&xg[4] = *(const float4*)&xb[516];
    *(float4*)&xo[0] = *(const float4*)&xb[768];  *(float4*)&xo[4] = *(const float4*)&xb[772];
    float* cb = &c[(size_t)b * 256 + jg];
    *(float4*)&cold[0] = *(const float4*)&cb[0];  *(float4*)&cold[4] = *(const float4*)&cb[4];
    float cn[8], hn[8];
    #pragma unroll
    for (int e = 0; e < 8; e++) {
        int jl = jj0 + e;
        float gi = Cs[bl][jl]      + xi[e];
        float gf = Cs[bl][16 + jl] + xf[e];
        float gg = Cs[bl][32 + jl] + xg[e];
        float go = Cs[bl][48 + jl] + xo[e];
        cn[e] = sigmoidf_(gf) * cold[e] + sigmoidf_(gi) * tanhf(gg);
        hn[e] = sigmoidf_(go) * tanhf(cn[e]);
    }
    *(float4*)&cb[0] = *(float4*)&cn[0];  *(float4*)&cb[4] = *(float4*)&cn[4];
    float* hb = &hseq[((size_t)b * Tsz + t) * 256 + jg];
    *(float4*)&hb[0] = *(float4*)&hn[0];  *(float4*)&hb[4] = *(float4*)&hn[4];
}

// ---------------- VSN ----------------
__global__ __launch_bounds__(256) void vsn_kernel(
    const float* __restrict__ x,
    const float* __restrict__ emb_w, const float* __restrict__ emb_b,
    const float* __restrict__ sel_w, const float* __restrict__ sel_b,
    float* __restrict__ h)
{
    int bt = blockIdx.x;
    int tid = threadIdx.x;
    __shared__ float xs[Fsz];
    __shared__ float wts[Fsz];
    if (tid < Fsz) xs[tid] = x[(size_t)bt * Fsz + tid];
    __syncthreads();
    if (tid == 0) {
        float lg[Fsz]; float mx = -1e30f;
        for (int f = 0; f < Fsz; f++) {
            float s = sel_b[f];
            for (int j = 0; j < Fsz; j++) s += xs[j] * sel_w[f * Fsz + j];
            lg[f] = s; mx = fmaxf(mx, s);
        }
        float den = 0.f;
        for (int f = 0; f < Fsz; f++) { lg[f] = expf(lg[f] - mx); den += lg[f]; }
        float inv = 1.0f / den;
        for (int f = 0; f < Fsz; f++) wts[f] = lg[f] * inv;
    }
    __syncthreads();
    float acc = 0.f;
#pragma unroll
    for (int f = 0; f < Fsz; f++)
        acc += wts[f] * (xs[f] * emb_w[f * Hsz + tid] + emb_b[f * Hsz + tid]);
    h[(size_t)bt * Hsz + tid] = acc;
}

// ---------------- LSTM step t=0 (gates = xp, c0=0) ----------------
__global__ __launch_bounds__(256) void lstm_step0(
    const float* __restrict__ xp, float* __restrict__ hseq, float* __restrict__ c)
{
    int b = blockIdx.x;
    int j = threadIdx.x;
    size_t xbase = (size_t)b * Tsz * 1024 + j;
    float gi = xp[xbase];
    float gg = xp[xbase + 512];
    float go = xp[xbase + 768];
    float cn = sigmoidf_(gi) * tanhf(gg);
    float hn = sigmoidf_(go) * tanhf(cn);
    c[(size_t)b * 256 + j] = cn;
    hseq[(size_t)b * Tsz * 256 + j] = hn;
}

// ---------------- NN SGEMM with row scaling (adj @ pe), fp32 ----------------
__global__ __launch_bounds__(256) void sgemm_nn_scale(
    const float* __restrict__ A, const float* __restrict__ Bm,
    const float* __restrict__ rowscale,
    float* __restrict__ C, int M, int N, int K)
{
    __shared__ float As[16][64];
    __shared__ float Bs[16][64];
    const int tid = threadIdx.x;
    const int m0 = blockIdx.y * 64;
    const int n0 = blockIdx.x * 64;
    const int lr = tid >> 2;
    const int lc = (tid & 3) << 2;
    const int br = tid >> 4;
    const int bc = (tid & 15) << 2;
    const int ty = tid >> 4, tx = tid & 15;
    float acc[4][4] = {};
    for (int k0 = 0; k0 < K; k0 += 16) {
        float4 a = *(const float4*)&A[(size_t)(m0 + lr) * K + k0 + lc];
        float4 b = *(const float4*)&Bm[(size_t)(k0 + br) * N + n0 + bc];
        As[lc + 0][lr] = a.x; As[lc + 1][lr] = a.y; As[lc + 2][lr] = a.z; As[lc + 3][lr] = a.w;
        Bs[br][bc + 0] = b.x; Bs[br][bc + 1] = b.y; Bs[br][bc + 2] = b.z; Bs[br][bc + 3] = b.w;
        __syncthreads();
#pragma unroll
        for (int kk = 0; kk < 16; kk++) {
            float ra[4], rb[4];
#pragma unroll
            for (int i = 0; i < 4; i++) ra[i] = As[kk][ty * 4 + i];
#pragma unroll
            for (int j = 0; j < 4; j++) rb[j] = Bs[kk][tx * 4 + j];
#pragma unroll
            for (int i = 0; i < 4; i++)
#pragma unroll
                for (int j = 0; j < 4; j++) acc[i][j] += ra[i] * rb[j];
        }
        __syncthreads();
    }
#pragma unroll
    for (int i = 0; i < 4; i++) {
        int m = m0 + ty * 4 + i;
        float sc = rowscale[m];
#pragma unroll
        for (int j = 0; j < 4; j++) {
            int n = n0 + tx * 4 + j;
            C[(size_t)m * N + n] = sc * acc[i][j];
        }
    }
}

// ---------------- q projection (last timestep) ----------------
__global__ __launch_bounds__(256) void qproj_kernel(
    const float* __restrict__ h, const float* __restrict__ Wq,
    const float* __restrict__ bq, float* __restrict__ q)
{
    int b = blockIdx.x, tid = threadIdx.x;
    __shared__ float hs[Hsz];
    hs[tid] = h[((size_t)b * Tsz + (Tsz - 1)) * Hsz + tid];
    __syncthreads();
    float s = bq[tid];
    const float* wrow = &Wq[(size_t)tid * Hsz];
#pragma unroll 8
    for (int k = 0; k < Hsz; k++) s += hs[k] * wrow[k];
    q[(size_t)b * Hsz + tid] = s;
}

// ---------------- attention (last query only) ----------------
__global__ __launch_bounds__(128) void attn_last_kernel(
    const float* __restrict__ q, const float* __restrict__ kv,
    float* __restrict__ o)
{
    int b = blockIdx.x, hd = blockIdx.y;
    int tid = threadIdx.x;
    __shared__ float qs[DHEAD];
    __shared__ float sc[Tsz];
    __shared__ float red[Tsz];
    if (tid < DHEAD) qs[tid] = q[(size_t)b * Hsz + hd * DHEAD + tid];
    __syncthreads();
    const float* kp = &kv[((size_t)b * Tsz + tid) * 512 + hd * DHEAD];
    float s = 0.f;
#pragma unroll 8
    for (int d = 0; d < DHEAD; d++) s += qs[d] * kp[d];
    s *= 0.125f;
    sc[tid] = s;
    red[tid] = s;
    __syncthreads();
    for (int off = 64; off; off >>= 1) {
        if (tid < off) red[tid] = fmaxf(red[tid], red[tid + off]);
        __syncthreads();
    }
    float mx = red[0];
    __syncthreads();
    float e = expf(sc[tid] - mx);
    sc[tid] = e;
    red[tid] = e;
    __syncthreads();
    for (int off = 64; off; off >>= 1) {
        if (tid < off) red[tid] += red[tid + off];
        __syncthreads();
    }
    float inv = 1.0f / red[0];
    __syncthreads();
    sc[tid] *= inv;
    __syncthreads();
    if (tid < DHEAD) {
        float acc = 0.f;
        for (int t = 0; t < Tsz; t++)
            acc += sc[t] * kv[((size_t)b * Tsz + t) * 512 + 256 + hd * DHEAD + tid];
        o[(size_t)b * Hsz + hd * DHEAD + tid] = acc;
    }
}

// ---------------- GNN helpers ----------------
__global__ __launch_bounds__(256) void scatter_kernel(
    const float* __restrict__ hidden, const int* __restrict__ sku,
    float* __restrict__ pe)
{
    int b = blockIdx.x, tid = threadIdx.x;
    pe[(size_t)sku[b] * Hsz + tid] = hidden[(size_t)b * Hsz + tid];
}

__global__ __launch_bounds__(256) void deg_kernel(
    const float* __restrict__ adj, float* __restrict__ scale)
{
    int p = blockIdx.x, tid = threadIdx.x;
    float s = 0.f;
    for (int j = tid; j < Psz; j += 256) s += adj[(size_t)p * Psz + j];
    __shared__ float red[256];
    red[tid] = s; __syncthreads();
    for (int off = 128; off; off >>= 1) {
        if (tid < off) red[tid] += red[tid + off];
        __syncthreads();
    }
    if (tid == 0) scale[p] = 1.0f / fmaxf(red[0], 1e-6f);
}

__global__ __launch_bounds__(256) void geluln_kernel(
    float* __restrict__ x, const float* __restrict__ g,
    const float* __restrict__ b)
{
    int p = blockIdx.x, tid = threadIdx.x;
    float v = x[(size_t)p * Hsz + tid];
    float ge = 0.5f * v * (1.0f + erff(v * 0.70710678118654752f));
    __shared__ float red[256];
    red[tid] = ge; __syncthreads();
    for (int off = 128; off; off >>= 1) {
        if (tid < off) red[tid] += red[tid + off];
        __syncthreads();
    }
    float mu = red[0] * (1.0f / Hsz);
    __syncthreads();
    float d = ge - mu;
    red[tid] = d * d; __syncthreads();
    for (int off = 128; off; off >>= 1) {
        if (tid < off) red[tid] += red[tid + off];
        __syncthreads();
    }
    float var = red[0] * (1.0f / Hsz);
    x[(size_t)p * Hsz + tid] = d * rsqrtf(var + 1e-5f) * g[tid] + b[tid];
}

// ---------------- gate + output head ----------------
__global__ __launch_bounds__(256) void final_kernel(
    const float* __restrict__ hidden, const float* __restrict__ trans,
    const int* __restrict__ sku,
    const float* __restrict__ gate_w, const float* __restrict__ gate_b,
    const float* __restrict__ out_w, const float* __restrict__ out_b,
    float* __restrict__ out)
{
    int b = blockIdx.x, tid = threadIdx.x;
    __shared__ float cat[512];
    cat[tid] = hidden[(size_t)b * Hsz + tid];
    cat[256 + tid] = trans[(size_t)sku[b] * Hsz + tid];
    __syncthreads();
    float s = gate_b[tid];
    const float* wrow = &gate_w[(size_t)tid * 512];
#pragma unroll 8
    for (int k = 0; k < 512; k++) s += cat[k] * wrow[k];
    float gt = 1.0f / (1.0f + expf(-s));
    float comb = gt * cat[256 + tid] + (1.0f - gt) * cat[tid];
    __shared__ float red[256];
    red[tid] = comb * out_w[tid];
    __syncthreads();
    for (int off = 128; off; off >>= 1) {
        if (tid < off) red[tid] += red[tid + off];
        __syncthreads();
    }
    if (tid == 0) out[b] = red[0] + out_b[0];
}

// ---------------- launch ----------------
extern "C" void kernel_launch(void* const* d_in, const int* in_sizes, int n_in,
                              void* d_out, int out_size)
{
    const float* x          = (const float*)d_in[0];
    const int*   sku        = (const int*)  d_in[1];
    const float* adj        = (const float*)d_in[2];
    const float* vsn_emb_w  = (const float*)d_in[3];
    const float* vsn_emb_b  = (const float*)d_in[4];
    const float* vsn_sel_w  = (const float*)d_in[5];
    const float* vsn_sel_b  = (const float*)d_in[6];
    const float* Wih0       = (const float*)d_in[7];
    const float* Whh0       = (const float*)d_in[8];
    const float* bih0       = (const float*)d_in[9];
    const float* bhh0       = (const float*)d_in[10];
    const float* Wih1       = (const float*)d_in[11];
    const float* Whh1       = (const float*)d_in[12];
    const float* bih1       = (const float*)d_in[13];
    const float* bhh1       = (const float*)d_in[14];
    const float* attn_in_w  = (const float*)d_in[15];
    const float* attn_in_b  = (const float*)d_in[16];
    const float* attn_out_w = (const float*)d_in[17];
    const float* attn_out_b = (const float*)d_in[18];
    const float* gnn_w      = (const float*)d_in[19];
    const float* gnn_b      = (const float*)d_in[20];
    const float* ln_g       = (const float*)d_in[21];
    const float* ln_b       = (const float*)d_in[22];
    const float* gate_w     = (const float*)d_in[23];
    const float* gate_b     = (const float*)d_in[24];
    const float* out_w      = (const float*)d_in[25];
    const float* out_b      = (const float*)d_in[26];
    float* out = (float*)d_out;

    static float *hP = nullptr, *xpP, *cP, *qP, *oP, *hidP, *peP, *degP, *aggP, *transP;
    if (!hP) {
        cudaGetSymbolAddress((void**)&hP, g_h);
        cudaGetSymbolAddress((void**)&xpP, g_xp);
        cudaGetSymbolAddress((void**)&cP, g_c);
        cudaGetSymbolAddress((void**)&qP, g_q);
        cudaGetSymbolAddress((void**)&oP, g_o);
        cudaGetSymbolAddress((void**)&hidP, g_hidden);
        cudaGetSymbolAddress((void**)&degP, g_degs);
        cudaGetSymbolAddress((void**)&peP, g_pe);
        cudaGetSymbolAddress((void**)&aggP, g_agg);
        cudaGetSymbolAddress((void**)&transP, g_trans);
    }

    // 1. VSN -> g_h (BT, 256)
    vsn_kernel<<<BT, 256>>>(x, vsn_emb_w, vsn_emb_b, vsn_sel_w, vsn_sel_b, hP);

    // 2. LSTM layer 0
    mm_nt_tf32<<<dim3(16, BT / 128), 256>>>(hP, Wih0, bih0, bhh0, xpP, 1024);
    lstm_step0<<<Bsz, 256>>>(xpP, hP, cP);
    for (int t = 1; t < Tsz; t++)
        lstm_tc<<<dim3(16, 8), 256>>>(xpP, hP, Whh0, cP, t);

    // 3. LSTM layer 1
    mm_nt_tf32<<<dim3(16, BT / 128), 256>>>(hP, Wih1, bih1, bhh1, xpP, 1024);
    lstm_step0<<<Bsz, 256>>>(xpP, hP, cP);
    for (int t = 1; t < Tsz; t++)
        lstm_tc<<<dim3(16, 8), 256>>>(xpP, hP, Whh1, cP, t);

    // 4. k,v projection (rows 256..767 of attn_in_w) -> g_xp as (BT, 512); q last step
    mm_nt_tf32<<<dim3(8, BT / 128), 256>>>(hP, attn_in_w + (size_t)Hsz * Hsz,
                                           attn_in_b + Hsz, nullptr, xpP, 512);
    qproj_kernel<<<Bsz, 256>>>(hP, attn_in_w, attn_in_b, qP);

    // 5. attention at last query
    attn_last_kernel<<<dim3(Bsz, NHEADS), 128>>>(qP, xpP, oP);

    // 6. output projection -> hidden (B, 256)
    mm_nt_tf32<<<dim3(4, Bsz / 128), 256>>>(oP, attn_out_w, attn_out_b, nullptr, hidP, 256);

    // 7. GNN
    cudaMemsetAsync(peP, 0, (size_t)Psz * Hsz * sizeof(float));
    scatter_kernel<<<Bsz, 256>>>(hidP, sku, peP);
    deg_kernel<<<Psz, 256>>>(adj, degP);
    sgemm_nn_scale<<<dim3(Hsz / 64, Psz / 64), 256>>>(adj, peP, degP, aggP, Psz, Hsz, Psz);
    mm_nt_tf32<<<dim3(4, Psz / 128), 256>>>(aggP, gnn_w, gnn_b, nullptr, transP, 256);
    geluln_kernel<<<Psz, 256>>>(transP, ln_g, ln_b);

    // 8. gate + head
    final_kernel<<<Bsz, 256>>>(hidP, transP, sku, gate_w, gate_b, out_w, out_b, out);
}

// round 5
// speedup vs baseline: 2.5556x; 1.2240x over previous
#include <cuda_runtime.h>
#include <cuda_bf16.h>
#include <math.h>
#include <stdint.h>

// Problem constants
#define Bsz 1024
#define Tsz 128
#define Fsz 9
#define Hsz 256
#define Psz 2048
#define NHEADS 4
#define DHEAD 64
#define BT (Bsz*Tsz)
#define NCTA 128

// ---------------- scratch (static device globals; no allocation) ----------------
__device__ float g_h[BT * Hsz];        // VSN out / LSTM hseq  [b*T+t][256]
__device__ float g_xp[BT * 4 * Hsz];   // xp precompute / kv buffer [b*T+t][1024]
__device__ float g_q[Bsz * Hsz];
__device__ float g_o[Bsz * Hsz];
__device__ float g_hidden[Bsz * Hsz];
__device__ float g_pe[Psz * Hsz];
__device__ float g_degs[Psz];
__device__ float g_agg[Psz * Hsz];
__device__ float g_trans[Psz * Hsz];

// grid barrier state (monotonic; 2^32 % 128 == 0 so wrap is clean)
__device__ unsigned g_bar_cnt;
__device__ volatile unsigned g_bar_gen;

__device__ __forceinline__ float sigmoidf_(float x) { return 1.0f / (1.0f + expf(-x)); }

// ---------------- tf32 mma.sync helpers (target-independent PTX, sm_80+) ----------------
__device__ __forceinline__ uint32_t f2tf32(float f) {
    uint32_t r;
    asm("cvt.rna.tf32.f32 %0, %1;" : "=r"(r) : "f"(f));
    return r;
}
__device__ __forceinline__ void mma_m16n8k8(float d[4], const uint32_t a[4], const uint32_t b[2]) {
    asm volatile(
        "mma.sync.aligned.m16n8k8.row.col.f32.tf32.tf32.f32 "
        "{%0,%1,%2,%3}, {%4,%5,%6,%7}, {%8,%9}, {%0,%1,%2,%3};"
        : "+f"(d[0]), "+f"(d[1]), "+f"(d[2]), "+f"(d[3])
        : "r"(a[0]), "r"(a[1]), "r"(a[2]), "r"(a[3]), "r"(b[0]), "r"(b[1]));
}

// ticket grid barrier: all NCTA CTAs co-resident (1 CTA/SM by smem, 128 <= 148 SMs)
__device__ __forceinline__ void grid_barrier() {
    __syncthreads();
    if (threadIdx.x == 0) {
        __threadfence();
        unsigned arr = atomicAdd(&g_bar_cnt, 1u);
        unsigned want = arr / NCTA + 1u;
        if ((arr % NCTA) == NCTA - 1u) {
            g_bar_gen = want;                 // release (after threadfence above)
        } else {
            while ((int)(g_bar_gen - want) < 0) {}
        }
        __threadfence();
    }
    __syncthreads();
}

// ================= persistent LSTM layer =================
// 128 CTAs = 16 b-tiles(64) x 8 n-tiles(32 j, all 4 gates). Whh slice resident in smem,
// cell state resident in registers. Grid barrier between timesteps.
// smem: As 64x260 u32 (66,560 B) | Bs 128x260 u32 (133,120 B) => 199,680 B dynamic.
// Cs (64x132 f32 = 33,792 B) aliases As for epilogue staging.
__global__ __launch_bounds__(256) void lstm_persist(
    const float* __restrict__ xp, float* __restrict__ hseq,
    const float* __restrict__ Whh)
{
    extern __shared__ char sbuf[];
    uint32_t (*As)[260] = (uint32_t(*)[260])sbuf;
    uint32_t (*Bs)[260] = (uint32_t(*)[260])(sbuf + 66560);
    float (*Cs)[132]    = (float(*)[132])sbuf;

    const int tid = threadIdx.x;
    const int wid = tid >> 5, lane = tid & 31;
    const int gID = lane >> 2, tig = lane & 3;
    const int wr = wid & 1, wc = wid >> 1;          // warp grid 2(M) x 4(N)
    const int m0 = (blockIdx.x >> 3) * 64;          // batch tile
    const int j0 = (blockIdx.x & 7) * 32;           // j tile

    // ---- preload Whh slice (once): smem row r -> gate=r>>5, jj=r&31 ----
    for (int i = tid; i < 128 * 64; i += 256) {     // 8192 float4
        int r = i >> 6, cc = (i & 63) << 2;
        int wrow = (r >> 5) * 256 + j0 + (r & 31);
        float4 v = *(const float4*)&Whh[(size_t)wrow * 256 + cc];
        uint32_t* p = &Bs[r][cc];
        p[0] = f2tf32(v.x); p[1] = f2tf32(v.y); p[2] = f2tf32(v.z); p[3] = f2tf32(v.w);
    }

    // per-thread epilogue slice: bl in [0,64), 8 contiguous j's
    const int bl = tid >> 2, jl0 = (tid & 3) * 8;
    const int b = m0 + bl;
    float creg[8];

    // ---- t = 0: gates = xp, c0 = 0 ----
    {
        const float* xb = &xp[((size_t)b * Tsz + 0) * 1024 + j0 + jl0];
        float xi[8], xg[8], xo[8], hn[8];
        *(float4*)&xi[0] = *(const float4*)&xb[0];    *(float4*)&xi[4] = *(const float4*)&xb[4];
        *(float4*)&xg[0] = *(const float4*)&xb[512];  *(float4*)&xg[4] = *(const float4*)&xb[516];
        *(float4*)&xo[0] = *(const float4*)&xb[768];  *(float4*)&xo[4] = *(const float4*)&xb[772];
        #pragma unroll
        for (int e = 0; e < 8; e++) {
            creg[e] = sigmoidf_(xi[e]) * tanhf(xg[e]);
            hn[e] = sigmoidf_(xo[e]) * tanhf(creg[e]);
        }
        float* hb = &hseq[((size_t)b * Tsz + 0) * 256 + j0 + jl0];
        *(float4*)&hb[0] = *(float4*)&hn[0];  *(float4*)&hb[4] = *(float4*)&hn[4];
    }
    grid_barrier();

    for (int t = 1; t < Tsz; t++) {
        // ---- stage h_{t-1} tile (64 x 256) as tf32 ----
        for (int i = tid; i < 64 * 64; i += 256) {  // 4096 float4
            int r = i >> 6, cc = (i & 63) << 2;
            float4 v = *(const float4*)&hseq[((size_t)(m0 + r) * Tsz + (t - 1)) * 256 + cc];
            uint32_t* p = &As[r][cc];
            p[0] = f2tf32(v.x); p[1] = f2tf32(v.y); p[2] = f2tf32(v.z); p[3] = f2tf32(v.w);
        }
        __syncthreads();

        // ---- MMA: M=64, N=128, K=256. warp tile 32x32 ----
        float d[2][4][4] = {};
        #pragma unroll 8
        for (int k8 = 0; k8 < 32; k8++) {
            uint32_t a[2][4], bfr[4][2];
            #pragma unroll
            for (int mi = 0; mi < 2; mi++) {
                int mr = wr * 32 + mi * 16;
                a[mi][0] = As[mr + gID][k8 * 8 + tig];
                a[mi][1] = As[mr + 8 + gID][k8 * 8 + tig];
                a[mi][2] = As[mr + gID][k8 * 8 + 4 + tig];
                a[mi][3] = As[mr + 8 + gID][k8 * 8 + 4 + tig];
            }
            #pragma unroll
            for (int ni = 0; ni < 4; ni++) {
                int nr = wc * 32 + ni * 8 + gID;
                bfr[ni][0] = Bs[nr][k8 * 8 + tig];
                bfr[ni][1] = Bs[nr][k8 * 8 + 4 + tig];
            }
            #pragma unroll
            for (int mi = 0; mi < 2; mi++)
                #pragma unroll
                for (int ni = 0; ni < 4; ni++)
                    mma_m16n8k8(d[mi][ni], a[mi], bfr[ni]);
        }
        __syncthreads();  // done reading As; Cs aliases it

        // ---- stage accumulators ----
        #pragma unroll
        for (int mi = 0; mi < 2; mi++) {
            int m = wr * 32 + mi * 16 + gID;
            #pragma unroll
            for (int ni = 0; ni < 4; ni++) {
                int n = wc * 32 + ni * 8 + tig * 2;
                *(float2*)&Cs[m][n]     = make_float2(d[mi][ni][0], d[mi][ni][1]);
                *(float2*)&Cs[m + 8][n] = make_float2(d[mi][ni][2], d[mi][ni][3]);
            }
        }
        __syncthreads();

        // ---- fused cell update ----
        const float* xb = &xp[((size_t)b * Tsz + t) * 1024 + j0 + jl0];
        float xi[8], xf[8], xg[8], xo[8], hn[8];
        *(float4*)&xi[0] = *(const float4*)&xb[0];    *(float4*)&xi[4] = *(const float4*)&xb[4];
        *(float4*)&xf[0] = *(const float4*)&xb[256];  *(float4*)&xf[4] = *(const float4*)&xb[260];
        *(float4*)&xg[0] = *(const float4*)&xb[512];  *(float4*)&xg[4] = *(const float4*)&xb[516];
        *(float4*)&xo[0] = *(const float4*)&xb[768];  *(float4*)&xo[4] = *(const float4*)&xb[772];
        #pragma unroll
        for (int e = 0; e < 8; e++) {
            int jl = jl0 + e;
            float gi = Cs[bl][jl]      + xi[e];
            float gf = Cs[bl][32 + jl] + xf[e];
            float gg = Cs[bl][64 + jl] + xg[e];
            float go = Cs[bl][96 + jl] + xo[e];
            creg[e] = sigmoidf_(gf) * creg[e] + sigmoidf_(gi) * tanhf(gg);
            hn[e] = sigmoidf_(go) * tanhf(creg[e]);
        }
        float* hb = &hseq[((size_t)b * Tsz + t) * 256 + j0 + jl0];
        *(float4*)&hb[0] = *(float4*)&hn[0];  *(float4*)&hb[4] = *(float4*)&hn[4];

        grid_barrier();
    }
}

// ================= mm_nt_tf32: C[m,n] = sum_k A[m,k]*W[n,k] + b1[n] + b2[n] =================
__global__ __launch_bounds__(256) void mm_nt_tf32(
    const float* __restrict__ A, const float* __restrict__ W,
    const float* __restrict__ b1, const float* __restrict__ b2,
    float* __restrict__ C, int Nall)
{
    __shared__ __align__(16) uint32_t As[128][36];
    __shared__ __align__(16) uint32_t Bs[64][36];
    const int tid = threadIdx.x;
    const int wid = tid >> 5, lane = tid & 31;
    const int gID = lane >> 2, tig = lane & 3;
    const int wr = wid & 3, wc = wid >> 2;
    const int m0 = blockIdx.y * 128, n0 = blockIdx.x * 64;
    float d[2][4][4] = {};

    for (int k0 = 0; k0 < 256; k0 += 32) {
        #pragma unroll
        for (int i = 0; i < 4; i++) {
            int idx = tid + i * 256;
            int r = idx >> 3, cc = (idx & 7) << 2;
            float4 v = *(const float4*)&A[(size_t)(m0 + r) * 256 + k0 + cc];
            uint32_t* p = &As[r][cc];
            p[0] = f2tf32(v.x); p[1] = f2tf32(v.y); p[2] = f2tf32(v.z); p[3] = f2tf32(v.w);
        }
        #pragma unroll
        for (int i = 0; i < 2; i++) {
            int idx = tid + i * 256;
            int r = idx >> 3, cc = (idx & 7) << 2;
            float4 v = *(const float4*)&W[(size_t)(n0 + r) * 256 + k0 + cc];
            uint32_t* p = &Bs[r][cc];
            p[0] = f2tf32(v.x); p[1] = f2tf32(v.y); p[2] = f2tf32(v.z); p[3] = f2tf32(v.w);
        }
        __syncthreads();
        #pragma unroll
        for (int k8 = 0; k8 < 4; k8++) {
            uint32_t a[2][4], b[4][2];
            #pragma unroll
            for (int mi = 0; mi < 2; mi++) {
                int mr = wr * 32 + mi * 16;
                a[mi][0] = As[mr + gID][k8 * 8 + tig];
                a[mi][1] = As[mr + 8 + gID][k8 * 8 + tig];
                a[mi][2] = As[mr + gID][k8 * 8 + 4 + tig];
                a[mi][3] = As[mr + 8 + gID][k8 * 8 + 4 + tig];
            }
            #pragma unroll
            for (int ni = 0; ni < 4; ni++) {
                int nr = wc * 32 + ni * 8 + gID;
                b[ni][0] = Bs[nr][k8 * 8 + tig];
                b[ni][1] = Bs[nr][k8 * 8 + 4 + tig];
            }
            #pragma unroll
            for (int mi = 0; mi < 2; mi++)
                #pragma unroll
                for (int ni = 0; ni < 4; ni++)
                    mma_m16n8k8(d[mi][ni], a[mi], b[ni]);
        }
        __syncthreads();
    }
    #pragma unroll
    for (int mi = 0; mi < 2; mi++) {
        int m = m0 + wr * 32 + mi * 16 + gID;
        #pragma unroll
        for (int ni = 0; ni < 4; ni++) {
            int n = n0 + wc * 32 + ni * 8 + tig * 2;
            float bb0 = 0.f, bb1 = 0.f;
            if (b1) { bb0 += b1[n]; bb1 += b1[n + 1]; }
            if (b2) { bb0 += b2[n]; bb1 += b2[n + 1]; }
            C[(size_t)m * Nall + n]       = d[mi][ni][0] + bb0;
            C[(size_t)m * Nall + n + 1]   = d[mi][ni][1] + bb1;
            C[(size_t)(m + 8) * Nall + n]     = d[mi][ni][2] + bb0;
            C[(size_t)(m + 8) * Nall + n + 1] = d[mi][ni][3] + bb1;
        }
    }
}

// ---------------- VSN ----------------
__global__ __launch_bounds__(256) void vsn_kernel(
    const float* __restrict__ x,
    const float* __restrict__ emb_w, const float* __restrict__ emb_b,
    const float* __restrict__ sel_w, const float* __restrict__ sel_b,
    float* __restrict__ h)
{
    int bt = blockIdx.x;
    int tid = threadIdx.x;
    __shared__ float xs[Fsz];
    __shared__ float wts[Fsz];
    if (tid < Fsz) xs[tid] = x[(size_t)bt * Fsz + tid];
    __syncthreads();
    if (tid == 0) {
        float lg[Fsz]; float mx = -1e30f;
        for (int f = 0; f < Fsz; f++) {
            float s = sel_b[f];
            for (int j = 0; j < Fsz; j++) s += xs[j] * sel_w[f * Fsz + j];
            lg[f] = s; mx = fmaxf(mx, s);
        }
        float den = 0.f;
        for (int f = 0; f < Fsz; f++) { lg[f] = expf(lg[f] - mx); den += lg[f]; }
        float inv = 1.0f / den;
        for (int f = 0; f < Fsz; f++) wts[f] = lg[f] * inv;
    }
    __syncthreads();
    float acc = 0.f;
#pragma unroll
    for (int f = 0; f < Fsz; f++)
        acc += wts[f] * (xs[f] * emb_w[f * Hsz + tid] + emb_b[f * Hsz + tid]);
    h[(size_t)bt * Hsz + tid] = acc;
}

// ---------------- NN SGEMM with row scaling (adj @ pe), fp32 ----------------
__global__ __launch_bounds__(256) void sgemm_nn_scale(
    const float* __restrict__ A, const float* __restrict__ Bm,
    const float* __restrict__ rowscale,
    float* __restrict__ C, int M, int N, int K)
{
    __shared__ float As[16][64];
    __shared__ float Bs[16][64];
    const int tid = threadIdx.x;
    const int m0 = blockIdx.y * 64;
    const int n0 = blockIdx.x * 64;
    const int lr = tid >> 2;
    const int lc = (tid & 3) << 2;
    const int br = tid >> 4;
    const int bc = (tid & 15) << 2;
    const int ty = tid >> 4, tx = tid & 15;
    float acc[4][4] = {};
    for (int k0 = 0; k0 < K; k0 += 16) {
        float4 a = *(const float4*)&A[(size_t)(m0 + lr) * K + k0 + lc];
        float4 b = *(const float4*)&Bm[(size_t)(k0 + br) * N + n0 + bc];
        As[lc + 0][lr] = a.x; As[lc + 1][lr] = a.y; As[lc + 2][lr] = a.z; As[lc + 3][lr] = a.w;
        Bs[br][bc + 0] = b.x; Bs[br][bc + 1] = b.y; Bs[br][bc + 2] = b.z; Bs[br][bc + 3] = b.w;
        __syncthreads();
#pragma unroll
        for (int kk = 0; kk < 16; kk++) {
            float ra[4], rb[4];
#pragma unroll
            for (int i = 0; i < 4; i++) ra[i] = As[kk][ty * 4 + i];
#pragma unroll
            for (int j = 0; j < 4; j++) rb[j] = Bs[kk][tx * 4 + j];
#pragma unroll
            for (int i = 0; i < 4; i++)
#pragma unroll
                for (int j = 0; j < 4; j++) acc[i][j] += ra[i] * rb[j];
        }
        __syncthreads();
    }
#pragma unroll
    for (int i = 0; i < 4; i++) {
        int m = m0 + ty * 4 + i;
        float sc = rowscale[m];
#pragma unroll
        for (int j = 0; j < 4; j++) {
            int n = n0 + tx * 4 + j;
            C[(size_t)m * N + n] = sc * acc[i][j];
        }
    }
}

// ---------------- q projection (last timestep) ----------------
__global__ __launch_bounds__(256) void qproj_kernel(
    const float* __restrict__ h, const float* __restrict__ Wq,
    const float* __restrict__ bq, float* __restrict__ q)
{
    int b = blockIdx.x, tid = threadIdx.x;
    __shared__ float hs[Hsz];
    hs[tid] = h[((size_t)b * Tsz + (Tsz - 1)) * Hsz + tid];
    __syncthreads();
    float s = bq[tid];
    const float* wrow = &Wq[(size_t)tid * Hsz];
#pragma unroll 8
    for (int k = 0; k < Hsz; k++) s += hs[k] * wrow[k];
    q[(size_t)b * Hsz + tid] = s;
}

// ---------------- attention (last query only) ----------------
__global__ __launch_bounds__(128) void attn_last_kernel(
    const float* __restrict__ q, const float* __restrict__ kv,
    float* __restrict__ o)
{
    int b = blockIdx.x, hd = blockIdx.y;
    int tid = threadIdx.x;
    __shared__ float qs[DHEAD];
    __shared__ float sc[Tsz];
    __shared__ float red[Tsz];
    if (tid < DHEAD) qs[tid] = q[(size_t)b * Hsz + hd * DHEAD + tid];
    __syncthreads();
    const float* kp = &kv[((size_t)b * Tsz + tid) * 512 + hd * DHEAD];
    float s = 0.f;
#pragma unroll 8
    for (int d = 0; d < DHEAD; d++) s += qs[d] * kp[d];
    s *= 0.125f;
    sc[tid] = s;
    red[tid] = s;
    __syncthreads();
    for (int off = 64; off; off >>= 1) {
        if (tid < off) red[tid] = fmaxf(red[tid], red[tid + off]);
        __syncthreads();
    }
    float mx = red[0];
    __syncthreads();
    float e = expf(sc[tid] - mx);
    sc[tid] = e;
    red[tid] = e;
    __syncthreads();
    for (int off = 64; off; off >>= 1) {
        if (tid < off) red[tid] += red[tid + off];
        __syncthreads();
    }
    float inv = 1.0f / red[0];
    __syncthreads();
    sc[tid] *= inv;
    __syncthreads();
    if (tid < DHEAD) {
        float acc = 0.f;
        for (int t = 0; t < Tsz; t++)
            acc += sc[t] * kv[((size_t)b * Tsz + t) * 512 + 256 + hd * DHEAD + tid];
        o[(size_t)b * Hsz + hd * DHEAD + tid] = acc;
    }
}

// ---------------- GNN helpers ----------------
__global__ __launch_bounds__(256) void scatter_kernel(
    const float* __restrict__ hidden, const int* __restrict__ sku,
    float* __restrict__ pe)
{
    int b = blockIdx.x, tid = threadIdx.x;
    pe[(size_t)sku[b] * Hsz + tid] = hidden[(size_t)b * Hsz + tid];
}

__global__ __launch_bounds__(256) void deg_kernel(
    const float* __restrict__ adj, float* __restrict__ scale)
{
    int p = blockIdx.x, tid = threadIdx.x;
    float s = 0.f;
    for (int j = tid; j < Psz; j += 256) s += adj[(size_t)p * Psz + j];
    __shared__ float red[256];
    red[tid] = s; __syncthreads();
    for (int off = 128; off; off >>= 1) {
        if (tid < off) red[tid] += red[tid + off];
        __syncthreads();
    }
    if (tid == 0) scale[p] = 1.0f / fmaxf(red[0], 1e-6f);
}

__global__ __launch_bounds__(256) void geluln_kernel(
    float* __restrict__ x, const float* __restrict__ g,
    const float* __restrict__ b)
{
    int p = blockIdx.x, tid = threadIdx.x;
    float v = x[(size_t)p * Hsz + tid];
    float ge = 0.5f * v * (1.0f + erff(v * 0.70710678118654752f));
    __shared__ float red[256];
    red[tid] = ge; __syncthreads();
    for (int off = 128; off; off >>= 1) {
        if (tid < off) red[tid] += red[tid + off];
        __syncthreads();
    }
    float mu = red[0] * (1.0f / Hsz);
    __syncthreads();
    float d = ge - mu;
    red[tid] = d * d; __syncthreads();
    for (int off = 128; off; off >>= 1) {
        if (tid < off) red[tid] += red[tid + off];
        __syncthreads();
    }
    float var = red[0] * (1.0f / Hsz);
    x[(size_t)p * Hsz + tid] = d * rsqrtf(var + 1e-5f) * g[tid] + b[tid];
}

// ---------------- gate + output head ----------------
__global__ __launch_bounds__(256) void final_kernel(
    const float* __restrict__ hidden, const float* __restrict__ trans,
    const int* __restrict__ sku,
    const float* __restrict__ gate_w, const float* __restrict__ gate_b,
    const float* __restrict__ out_w, const float* __restrict__ out_b,
    float* __restrict__ out)
{
    int b = blockIdx.x, tid = threadIdx.x;
    __shared__ float cat[512];
    cat[tid] = hidden[(size_t)b * Hsz + tid];
    cat[256 + tid] = trans[(size_t)sku[b] * Hsz + tid];
    __syncthreads();
    float s = gate_b[tid];
    const float* wrow = &gate_w[(size_t)tid * 512];
#pragma unroll 8
    for (int k = 0; k < 512; k++) s += cat[k] * wrow[k];
    float gt = 1.0f / (1.0f + expf(-s));
    float comb = gt * cat[256 + tid] + (1.0f - gt) * cat[tid];
    __shared__ float red[256];
    red[tid] = comb * out_w[tid];
    __syncthreads();
    for (int off = 128; off; off >>= 1) {
        if (tid < off) red[tid] += red[tid + off];
        __syncthreads();
    }
    if (tid == 0) out[b] = red[0] + out_b[0];
}

// ---------------- launch ----------------
#define LSTM_SMEM 199680

extern "C" void kernel_launch(void* const* d_in, const int* in_sizes, int n_in,
                              void* d_out, int out_size)
{
    const float* x          = (const float*)d_in[0];
    const int*   sku        = (const int*)  d_in[1];
    const float* adj        = (const float*)d_in[2];
    const float* vsn_emb_w  = (const float*)d_in[3];
    const float* vsn_emb_b  = (const float*)d_in[4];
    const float* vsn_sel_w  = (const float*)d_in[5];
    const float* vsn_sel_b  = (const float*)d_in[6];
    const float* Wih0       = (const float*)d_in[7];
    const float* Whh0       = (const float*)d_in[8];
    const float* bih0       = (const float*)d_in[9];
    const float* bhh0       = (const float*)d_in[10];
    const float* Wih1       = (const float*)d_in[11];
    const float* Whh1       = (const float*)d_in[12];
    const float* bih1       = (const float*)d_in[13];
    const float* bhh1       = (const float*)d_in[14];
    const float* attn_in_w  = (const float*)d_in[15];
    const float* attn_in_b  = (const float*)d_in[16];
    const float* attn_out_w = (const float*)d_in[17];
    const float* attn_out_b = (const float*)d_in[18];
    const float* gnn_w      = (const float*)d_in[19];
    const float* gnn_b      = (const float*)d_in[20];
    const float* ln_g       = (const float*)d_in[21];
    const float* ln_b       = (const float*)d_in[22];
    const float* gate_w     = (const float*)d_in[23];
    const float* gate_b     = (const float*)d_in[24];
    const float* out_w      = (const float*)d_in[25];
    const float* out_b      = (const float*)d_in[26];
    float* out = (float*)d_out;

    static float *hP = nullptr, *xpP, *qP, *oP, *hidP, *peP, *degP, *aggP, *transP;
    if (!hP) {
        cudaGetSymbolAddress((void**)&hP, g_h);
        cudaGetSymbolAddress((void**)&xpP, g_xp);
        cudaGetSymbolAddress((void**)&qP, g_q);
        cudaGetSymbolAddress((void**)&oP, g_o);
        cudaGetSymbolAddress((void**)&hidP, g_hidden);
        cudaGetSymbolAddress((void**)&degP, g_degs);
        cudaGetSymbolAddress((void**)&peP, g_pe);
        cudaGetSymbolAddress((void**)&aggP, g_agg);
        cudaGetSymbolAddress((void**)&transP, g_trans);
        cudaFuncSetAttribute(lstm_persist, cudaFuncAttributeMaxDynamicSharedMemorySize, LSTM_SMEM);
    }

    // 1. VSN -> g_h (BT, 256)
    vsn_kernel<<<BT, 256>>>(x, vsn_emb_w, vsn_emb_b, vsn_sel_w, vsn_sel_b, hP);

    // 2. LSTM layer 0 (persistent: all 128 steps in one launch)
    mm_nt_tf32<<<dim3(16, BT / 128), 256>>>(hP, Wih0, bih0, bhh0, xpP, 1024);
    lstm_persist<<<NCTA, 256, LSTM_SMEM>>>(xpP, hP, Whh0);

    // 3. LSTM layer 1
    mm_nt_tf32<<<dim3(16, BT / 128), 256>>>(hP, Wih1, bih1, bhh1, xpP, 1024);
    lstm_persist<<<NCTA, 256, LSTM_SMEM>>>(xpP, hP, Whh1);

    // 4. k,v projection -> g_xp as (BT, 512); q only at last timestep
    mm_nt_tf32<<<dim3(8, BT / 128), 256>>>(hP, attn_in_w + (size_t)Hsz * Hsz,
                                           attn_in_b + Hsz, nullptr, xpP, 512);
    qproj_kernel<<<Bsz, 256>>>(hP, attn_in_w, attn_in_b, qP);

    // 5. attention at last query
    attn_last_kernel<<<dim3(Bsz, NHEADS), 128>>>(qP, xpP, oP);

    // 6. output projection -> hidden (B, 256)
    mm_nt_tf32<<<dim3(4, Bsz / 128), 256>>>(oP, attn_out_w, attn_out_b, nullptr, hidP, 256);

    // 7. GNN
    cudaMemsetAsync(peP, 0, (size_t)Psz * Hsz * sizeof(float));
    scatter_kernel<<<Bsz, 256>>>(hidP, sku, peP);
    deg_kernel<<<Psz, 256>>>(adj, degP);
    sgemm_nn_scale<<<dim3(Hsz / 64, Psz / 64), 256>>>(adj, peP, degP, aggP, Psz, Hsz, Psz);
    mm_nt_tf32<<<dim3(4, Psz / 128), 256>>>(aggP, gnn_w, gnn_b, nullptr, transP, 256);
    geluln_kernel<<<Psz, 256>>>(transP, ln_g, ln_b);

    // 8. gate + head
    final_kernel<<<Bsz, 256>>>(hidP, transP, sku, gate_w, gate_b, out_w, out_b, out);
}